// round 1
// baseline (speedup 1.0000x reference)
#include <cuda_runtime.h>
#include <math.h>

#define BATCH 2
#define NCH   8
#define HI    256
#define HS    64
#define HW    4096   // 64*64
#define CDIM  256

// ---------------- scratch (static __device__, no allocations) ----------------
// side 0 = target, side 1 = source. g_featT normalized in place after k_mean.
__device__ float g_featT[2][BATCH][HW][CDIM];   // 16 MB
__device__ float g_col[2][BATCH][HW][3];
__device__ int   g_lab[2][BATCH][HW];
__device__ int   g_list[2][BATCH][NCH][HW];
__device__ int   g_cnt[2][BATCH][NCH];
__device__ float g_mean[2][BATCH][NCH][CDIM];
__device__ float g_canvas[BATCH][3][HW];

// ---------------- K1: labels (nearest), colors (bilinear down), zero canvas --
__global__ void k_pre(const float* __restrict__ toh, const float* __restrict__ soh,
                      const float* __restrict__ trgb, const float* __restrict__ srgb)
{
    int pix = blockIdx.x * blockDim.x + threadIdx.x;
    int b = blockIdx.y;
    if (pix >= HW) return;
    int y = pix >> 6, x = pix & 63;
    int y4 = y * 4, x4 = x * 4;

    // nearest-down label at (4y, 4x): floor(d*256/64) = 4d
    int tl = 0, sl = 0;
#pragma unroll
    for (int ch = 0; ch < NCH; ch++) {
        size_t o = ((size_t)(b * NCH + ch) * HI + y4) * HI + x4;
        if (toh[o] > 0.f) tl = ch;
        if (soh[o] > 0.f) sl = ch;
    }
    g_lab[0][b][pix] = tl;
    g_lab[1][b][pix] = sl;

    // bilinear downsample 256->64, half-pixel: src = 4d + 1.5 -> avg of 2x2 at (+1,+2)
#pragma unroll
    for (int ch = 0; ch < 3; ch++) {
        size_t base = ((size_t)(b * 3 + ch) * HI + (y4 + 1)) * HI + (x4 + 1);
        g_col[0][b][pix][ch] = 0.25f * (trgb[base] + trgb[base + 1] + trgb[base + HI] + trgb[base + HI + 1]);
        g_col[1][b][pix][ch] = 0.25f * (srgb[base] + srgb[base + 1] + srgb[base + HI] + srgb[base + HI + 1]);
    }
    g_canvas[b][0][pix] = 0.f;
    g_canvas[b][1][pix] = 0.f;
    g_canvas[b][2][pix] = 0.f;
}

// ---------------- K2: transpose features [b][ch][pix] -> [side][b][pix][ch] --
__global__ void k_transpose(const float* __restrict__ tfeat, const float* __restrict__ sfeat)
{
    __shared__ float tile[32][33];
    int side = blockIdx.z >> 1;
    int b    = blockIdx.z & 1;
    const float* in = side ? sfeat : tfeat;
    int pix0 = blockIdx.x * 32, ch0 = blockIdx.y * 32;
    int tx = threadIdx.x, ty = threadIdx.y;  // (32, 8)
#pragma unroll
    for (int i = 0; i < 32; i += 8)
        tile[ty + i][tx] = in[((size_t)(b * CDIM + ch0 + ty + i)) * HW + pix0 + tx];
    __syncthreads();
#pragma unroll
    for (int i = 0; i < 32; i += 8)
        g_featT[side][b][pix0 + ty + i][ch0 + tx] = tile[tx][ty + i];
}

// ---------------- K3: deterministic order-preserving per-class compaction ----
__global__ void k_compact()
{
    int id = blockIdx.x;               // [0,32): side*16 + b*8 + cls
    int cls = id & 7;
    int b   = (id >> 3) & 1;
    int side = id >> 4;
    int lane = threadIdx.x;
    int base = 0;
    for (int start = 0; start < HW; start += 32) {
        int p = start + lane;
        bool m = (g_lab[side][b][p] == cls);
        unsigned bal = __ballot_sync(0xffffffffu, m);
        if (m) g_list[side][b][cls][base + __popc(bal & ((1u << lane) - 1u))] = p;
        base += __popc(bal);
    }
    if (lane == 0) g_cnt[side][b][cls] = base;
}

// ---------------- K4: per-(side,b,class) masked channel means ----------------
__global__ void k_mean()
{
    int id = blockIdx.x;
    int cls = id & 7;
    int b   = (id >> 3) & 1;
    int side = id >> 4;
    int ch = threadIdx.x;
    int n = g_cnt[side][b][cls];
    const int* __restrict__ lst = g_list[side][b][cls];
    float s = 0.f;
    for (int i = 0; i < n; i++)
        s += g_featT[side][b][lst[i]][ch];
    g_mean[side][b][cls][ch] = s / (float)max(n, 1);
}

// ---------------- K5: center + per-pixel L2 normalize (in place) -------------
__global__ void k_norm()
{
    int pix = blockIdx.x, b = blockIdx.y, side = blockIdx.z;
    int lab = g_lab[side][b][pix];
    if (lab == 0) return;   // class-0 pixels never used
    int tid = threadIdx.x;
    float v = g_featT[side][b][pix][tid] - g_mean[side][b][lab][tid];
    float sq = v * v;
#pragma unroll
    for (int off = 16; off; off >>= 1) sq += __shfl_xor_sync(0xffffffffu, sq, off);
    __shared__ float ws[8];
    __shared__ float total;
    if ((tid & 31) == 0) ws[tid >> 5] = sq;
    __syncthreads();
    if (tid < 8) {
        float t = ws[tid];
#pragma unroll
        for (int off = 4; off; off >>= 1) t += __shfl_xor_sync(0xffu, t, off);
        if (tid == 0) total = t;
    }
    __syncthreads();
    int n = g_cnt[side][b][lab];
    float scale = (n == 1) ? 1.f : 1.f / fmaxf(sqrtf(total), 1e-12f);
    g_featT[side][b][pix][tid] = v * scale;
}

// ---------------- K6: fused masked attention + online softmax ----------------
#define TPB 16   // targets per block
#define CS  32   // source chunk in smem

__global__ void __launch_bounds__(256) k_attn()
{
    __shared__ float S[CS][CDIM];   // 32 KB source feature chunk
    __shared__ float SC[CS][4];     // source colors

    int cls = blockIdx.y + 1;       // classes 1..7
    int b   = blockIdx.z;
    int ntT = g_cnt[0][b][cls];
    int t0  = blockIdx.x * TPB;
    if (t0 >= ntT) return;

    int scnt = g_cnt[1][b][cls];
    int srcSide = (scnt < 9) ? 0 : 1;       // use_self branch
    int ns = g_cnt[srcSide][b][cls];
    const int* __restrict__ slist = g_list[srcSide][b][cls];

    int wid = threadIdx.x >> 5, lane = threadIdx.x & 31;
    // lane-channel mapping: conflict-free LDS.128 (lanes 0..7 cover words 0..31)
    int o1 = lane * 4, o2 = 128 + lane * 4;

    int ti0 = t0 + wid * 2, ti1 = ti0 + 1;
    bool act0 = ti0 < ntT, act1 = ti1 < ntT;
    int tp0 = act0 ? g_list[0][b][cls][ti0] : 0;
    int tp1 = act1 ? g_list[0][b][cls][ti1] : 0;

    float4 a0l = *(const float4*)&g_featT[0][b][tp0][o1];
    float4 a0h = *(const float4*)&g_featT[0][b][tp0][o2];
    float4 a1l = *(const float4*)&g_featT[0][b][tp1][o1];
    float4 a1h = *(const float4*)&g_featT[0][b][tp1][o2];

    float m0 = -1e30f, l0 = 0.f, x0 = 0.f, y0 = 0.f, z0 = 0.f;
    float m1 = -1e30f, l1 = 0.f, x1 = 0.f, y1 = 0.f, z1 = 0.f;

    for (int sc0 = 0; sc0 < ns; sc0 += CS) {
        int n = min(CS, ns - sc0);
        // cooperative load: warp w fills source vecs w*4 .. w*4+3
#pragma unroll
        for (int jj = 0; jj < 4; jj++) {
            int j = wid * 4 + jj;
            if (j < n) {
                int sp = slist[sc0 + j];
                *(float4*)&S[j][o1] = *(const float4*)&g_featT[srcSide][b][sp][o1];
                *(float4*)&S[j][o2] = *(const float4*)&g_featT[srcSide][b][sp][o2];
                if (lane < 3) SC[j][lane] = g_col[srcSide][b][sp][lane];
            }
        }
        __syncthreads();

        for (int j = 0; j < n; j++) {
            float4 ul = *(const float4*)&S[j][o1];
            float4 uh = *(const float4*)&S[j][o2];
            float d0 = a0l.x*ul.x + a0l.y*ul.y + a0l.z*ul.z + a0l.w*ul.w
                     + a0h.x*uh.x + a0h.y*uh.y + a0h.z*uh.z + a0h.w*uh.w;
            float d1 = a1l.x*ul.x + a1l.y*ul.y + a1l.z*ul.z + a1l.w*ul.w
                     + a1h.x*uh.x + a1h.y*uh.y + a1h.z*uh.z + a1h.w*uh.w;
#pragma unroll
            for (int off = 16; off; off >>= 1) {
                d0 += __shfl_xor_sync(0xffffffffu, d0, off);
                d1 += __shfl_xor_sync(0xffffffffu, d1, off);
            }
            float cx = SC[j][0], cy = SC[j][1], cz = SC[j][2];
            if (d0 <= m0) {            // common case: no max update, 1 exp
                float p = __expf(d0 - m0);
                l0 += p; x0 += p * cx; y0 += p * cy; z0 += p * cz;
            } else {
                float al = __expf(m0 - d0);
                l0 = l0 * al + 1.f; x0 = x0 * al + cx; y0 = y0 * al + cy; z0 = z0 * al + cz;
                m0 = d0;
            }
            if (d1 <= m1) {
                float p = __expf(d1 - m1);
                l1 += p; x1 += p * cx; y1 += p * cy; z1 += p * cz;
            } else {
                float al = __expf(m1 - d1);
                l1 = l1 * al + 1.f; x1 = x1 * al + cx; y1 = y1 * al + cy; z1 = z1 * al + cz;
                m1 = d1;
            }
        }
        __syncthreads();
    }

    if (lane == 0) {
        if (act0) {
            float inv = 1.f / l0;
            g_canvas[b][0][tp0] = x0 * inv;
            g_canvas[b][1][tp0] = y0 * inv;
            g_canvas[b][2][tp0] = z0 * inv;
        }
        if (act1) {
            float inv = 1.f / l1;
            g_canvas[b][0][tp1] = x1 * inv;
            g_canvas[b][1][tp1] = y1 * inv;
            g_canvas[b][2][tp1] = z1 * inv;
        }
    }
}

// ---------------- K7: bilinear 64->256 upsample + clip -----------------------
__global__ void k_up(float* __restrict__ out)
{
    int idx = blockIdx.x * blockDim.x + threadIdx.x;
    if (idx >= BATCH * 3 * HI * HI) return;
    int ox = idx & 255;
    int oy = (idx >> 8) & 255;
    int bc = idx >> 16;
    int c = bc % 3, b = bc / 3;
    float sy = oy * 0.25f - 0.375f;
    float sx = ox * 0.25f - 0.375f;
    int iy = (int)floorf(sy), ix = (int)floorf(sx);
    float wy = sy - (float)iy, wx = sx - (float)ix;
    int ya = max(iy, 0), yb = min(iy + 1, HS - 1);
    int xa = max(ix, 0), xb = min(ix + 1, HS - 1);
    const float* __restrict__ P = g_canvas[b][c];
    float v00 = P[ya * HS + xa], v01 = P[ya * HS + xb];
    float v10 = P[yb * HS + xa], v11 = P[yb * HS + xb];
    float v = (1.f - wy) * ((1.f - wx) * v00 + wx * v01)
            +        wy  * ((1.f - wx) * v10 + wx * v11);
    out[idx] = fminf(fmaxf(v, -1.f), 1.f);
}

// ---------------- launch -----------------------------------------------------
extern "C" void kernel_launch(void* const* d_in, const int* in_sizes, int n_in,
                              void* d_out, int out_size)
{
    const float* src_rgb = (const float*)d_in[0];
    const float* tgt_rgb = (const float*)d_in[1];
    const float* src_oh  = (const float*)d_in[2];
    const float* tgt_oh  = (const float*)d_in[3];
    const float* t_feat  = (const float*)d_in[4];
    const float* s_feat  = (const float*)d_in[5];
    float* out = (float*)d_out;

    k_pre<<<dim3(HW / 256, BATCH), 256>>>(tgt_oh, src_oh, tgt_rgb, src_rgb);
    k_transpose<<<dim3(HW / 32, CDIM / 32, 2 * BATCH), dim3(32, 8)>>>(t_feat, s_feat);
    k_compact<<<2 * BATCH * NCH, 32>>>();
    k_mean<<<2 * BATCH * NCH, 256>>>();
    k_norm<<<dim3(HW, BATCH, 2), 256>>>();
    k_attn<<<dim3(HW / TPB, NCH - 1, BATCH), 256>>>();
    k_up<<<(BATCH * 3 * HI * HI) / 256, 256>>>(out);
}